// round 1
// baseline (speedup 1.0000x reference)
#include <cuda_runtime.h>

#define NF 4096
#define D 128
#define NBINS 101
#define TILE 128
#define KC 32
#define KST 36      // smem row stride (pad 4) -> bank residual 4
#define THREADS 256

__device__ float g_hist[2 * NBINS];   // [0..100] pos, [101..201] neg
__device__ int g_is64;

// Zero accumulators + sniff class dtype (int64 vs int32).
__global__ void prep_kernel(const int* cls32) {
    int t = threadIdx.x;
    if (t < 2 * NBINS) g_hist[t] = 0.0f;
    if (t == 0) {
        int nz = 0;
        // classes are 0..31; if dtype is int64 (LE), every odd 32-bit word is 0.
        for (int i = 1; i < 256; i += 2) nz |= cls32[i];
        g_is64 = (nz == 0) ? 1 : 0;
    }
}

__global__ __launch_bounds__(THREADS, 2)
void pair_hist_kernel(const float* __restrict__ F, const void* __restrict__ cls_raw) {
    const int bj = blockIdx.x;
    const int bi = blockIdx.y;
    if (bj < bi) return;   // upper-triangular tiles only

    __shared__ float As[TILE * KST];
    __shared__ float Bs[TILE * KST];
    __shared__ float whist[8][2 * NBINS];
    __shared__ int clsA[TILE], clsB[TILE];

    const int t    = threadIdx.x;
    const int tx   = t & 15;       // j direction
    const int ty   = t >> 4;       // i direction
    const int warp = t >> 5;

    // zero per-warp histograms
    for (int i = t; i < 8 * 2 * NBINS; i += THREADS)
        (&whist[0][0])[i] = 0.0f;

    if (t < TILE) {
        int va, vb;
        if (g_is64) {
            const long long* c = (const long long*)cls_raw;
            va = (int)c[bi * TILE + t];
            vb = (int)c[bj * TILE + t];
        } else {
            const int* c = (const int*)cls_raw;
            va = c[bi * TILE + t];
            vb = c[bj * TILE + t];
        }
        clsA[t] = va;
        clsB[t] = vb;
    }

    float acc[8][8];
#pragma unroll
    for (int m = 0; m < 8; m++)
#pragma unroll
        for (int n = 0; n < 8; n++) acc[m][n] = 0.0f;

    const float* Arow = F + (size_t)bi * TILE * D;
    const float* Brow = F + (size_t)bj * TILE * D;

    for (int kc = 0; kc < D; kc += KC) {
        __syncthreads();   // prev compute done (also covers whist/cls init on iter 0)
        // Load 128 rows x 32 floats for A and B tiles. 1024 float4 each, 4/thread.
#pragma unroll
        for (int it = 0; it < 4; it++) {
            int l = it * 256 + t;   // 0..1023
            int r = l >> 3;         // row 0..127
            int q = l & 7;          // float4 slot within 32-float chunk
            float4 va = *reinterpret_cast<const float4*>(Arow + r * D + kc + q * 4);
            float4 vb = *reinterpret_cast<const float4*>(Brow + r * D + kc + q * 4);
            *reinterpret_cast<float4*>(&As[r * KST + q * 4]) = va;
            *reinterpret_cast<float4*>(&Bs[r * KST + q * 4]) = vb;
        }
        __syncthreads();

#pragma unroll 4
        for (int k = 0; k < KC; k++) {
            float a[8], b[8];
#pragma unroll
            for (int m = 0; m < 8; m++) a[m] = As[(ty + 16 * m) * KST + k];
#pragma unroll
            for (int n = 0; n < 8; n++) b[n] = Bs[(tx + 16 * n) * KST + k];
#pragma unroll
            for (int m = 0; m < 8; m++)
#pragma unroll
                for (int n = 0; n < 8; n++)
                    acc[m][n] = fmaf(a[m], b[n], acc[m][n]);
        }
    }

    // ---- binning into per-warp smem histograms ----
    float* hw = whist[warp];
    const bool diag = (bi == bj);

#pragma unroll
    for (int m = 0; m < 8; m++) {
        const int il = ty + 16 * m;
        const int ci = clsA[il];
#pragma unroll
        for (int n = 0; n < 8; n++) {
            const int jl = tx + 16 * n;
            if (diag && jl <= il) continue;   // strict upper triangle globally
            float s = acc[m][n];
            // pos = (s+1)/step ; step = 2/100. Continuous triangular kernel,
            // so fmaf(s,50,50) matches reference within negligible perturbation.
            float posf = fmaf(s, 50.0f, 50.0f);
            int idx = (int)floorf(posf);
            idx = max(0, min(idx, NBINS - 1));
            float frac = posf - (float)idx;
            int off = (ci == clsB[jl]) ? 0 : NBINS;
            atomicAdd(&hw[off + idx], 1.0f - frac);
            atomicAdd(&hw[off + min(idx + 1, NBINS - 1)], frac);
        }
    }

    __syncthreads();
    // reduce 8 warp copies -> global accumulators
    for (int i = t; i < 2 * NBINS; i += THREADS) {
        float s = 0.0f;
#pragma unroll
        for (int w = 0; w < 8; w++) s += whist[w][i];
        atomicAdd(&g_hist[i], s);
    }
}

__global__ void finalize_kernel(float* out) {
    if (threadIdx.x == 0) {
        double Sp = 0.0, Sn = 0.0;
        for (int i = 0; i < NBINS; i++) {
            Sp += (double)g_hist[i];
            Sn += (double)g_hist[NBINS + i];
        }
        if (Sp <= 0.0) Sp = 1.0;
        if (Sn <= 0.0) Sn = 1.0;
        double cdf = 0.0, loss = 0.0;
        for (int j = 0; j < NBINS; j++) {
            cdf  += (double)g_hist[j] / Sp;
            loss += ((double)g_hist[NBINS + j] / Sn) * cdf;
        }
        out[0] = (float)loss;
    }
}

extern "C" void kernel_launch(void* const* d_in, const int* in_sizes, int n_in,
                              void* d_out, int out_size) {
    const float* F  = (const float*)d_in[0];
    const void* cls = d_in[1];
    (void)in_sizes; (void)n_in; (void)out_size;

    prep_kernel<<<1, 256>>>((const int*)cls);

    dim3 grid(NF / TILE, NF / TILE);   // 32 x 32, lower-tri blocks early-exit
    pair_hist_kernel<<<grid, THREADS>>>(F, cls);

    finalize_kernel<<<1, 32>>>((float*)d_out);
}

// round 2
// speedup vs baseline: 1.1302x; 1.1302x over previous
#include <cuda_runtime.h>

#define NF 4096
#define D 128
#define NBINS 101
#define NB2 (2 * NBINS)
#define TILE 128
#define KC 32
#define KST 36      // smem row stride (pad 4), multiple of 4 for float4 STS
#define THREADS 256
#define NHCOPY 4    // shared histogram copies (warps w and w+4 share copy w&3)
#define QSCALE 262144.0f          // 2^18
#define QMASK ((1ULL << 40) - 1ULL)

__device__ float g_cnt[NB2];   // per-bin pair counts (float, integer-exact < 2^24)
__device__ float g_frc[NB2];   // per-bin sum of frac
__device__ int g_is64;

// Zero accumulators + sniff class dtype (int64 vs int32) in parallel.
__global__ void prep_kernel(const int* cls32) {
    int t = threadIdx.x;
    if (t < NB2) { g_cnt[t] = 0.0f; g_frc[t] = 0.0f; }
    if (t < 32) {
        // classes are 0..31; if dtype is int64 (LE), odd 32-bit words are 0.
        int v = cls32[2 * t + 1];
        unsigned bal = __ballot_sync(0xffffffffu, v != 0);
        if (t == 0) g_is64 = (bal == 0) ? 1 : 0;
    }
}

__global__ __launch_bounds__(THREADS, 2)
void pair_hist_kernel(const float* __restrict__ F, const void* __restrict__ cls_raw) {
    const int bj = blockIdx.x;
    const int bi = blockIdx.y;
    if (bj < bi) return;   // upper-triangular tiles only

    __shared__ float As[TILE * KST];
    __shared__ float Bs[TILE * KST];
    __shared__ unsigned long long whist[NHCOPY][NB2];
    __shared__ int clsA[TILE], clsB[TILE];

    const int t    = threadIdx.x;
    const int tx   = t & 15;       // j direction
    const int ty   = t >> 4;       // i direction
    const int warp = t >> 5;
    const int lane = t & 31;

    // zero shared histogram copies
    for (int i = t; i < NHCOPY * NB2; i += THREADS)
        (&whist[0][0])[i] = 0ULL;

    if (t < TILE) {
        int va, vb;
        if (g_is64) {
            const long long* c = (const long long*)cls_raw;
            va = (int)c[bi * TILE + t];
            vb = (int)c[bj * TILE + t];
        } else {
            const int* c = (const int*)cls_raw;
            va = c[bi * TILE + t];
            vb = c[bj * TILE + t];
        }
        clsA[t] = va;
        clsB[t] = vb;
    }

    float acc[8][8];
#pragma unroll
    for (int m = 0; m < 8; m++)
#pragma unroll
        for (int n = 0; n < 8; n++) acc[m][n] = 0.0f;

    const float* Arow = F + (size_t)bi * TILE * D;
    const float* Brow = F + (size_t)bj * TILE * D;

    for (int kc = 0; kc < D; kc += KC) {
        __syncthreads();   // prev compute done (also covers whist/cls init on iter 0)
#pragma unroll
        for (int it = 0; it < 4; it++) {
            int l = it * 256 + t;   // 0..1023
            int r = l >> 3;         // row 0..127
            int q = l & 7;          // float4 slot within 32-float chunk
            float4 va = *reinterpret_cast<const float4*>(Arow + r * D + kc + q * 4);
            float4 vb = *reinterpret_cast<const float4*>(Brow + r * D + kc + q * 4);
            *reinterpret_cast<float4*>(&As[r * KST + q * 4]) = va;
            *reinterpret_cast<float4*>(&Bs[r * KST + q * 4]) = vb;
        }
        __syncthreads();

#pragma unroll 4
        for (int k = 0; k < KC; k++) {
            float a[8], b[8];
#pragma unroll
            for (int m = 0; m < 8; m++) a[m] = As[(ty + 16 * m) * KST + k];
#pragma unroll
            for (int n = 0; n < 8; n++) b[n] = Bs[(tx + 16 * n) * KST + k];
#pragma unroll
            for (int m = 0; m < 8; m++)
#pragma unroll
                for (int n = 0; n < 8; n++)
                    acc[m][n] = fmaf(a[m], b[n], acc[m][n]);
        }
    }

    // ---- warp-aggregated binning ----
    // Triangular kernel decomposed: bin idx gets (count=1, frac); finalize
    // reconstructs hist[b] = c[b] - f[b] + f[b-1]  (hist[100] = c[100] + f[99]).
    unsigned long long* hw = whist[warp & (NHCOPY - 1)];
    const bool diag = (bi == bj);

#pragma unroll
    for (int m = 0; m < 8; m++) {
        const int il = ty + 16 * m;
        const int ci = clsA[il];
#pragma unroll
        for (int n = 0; n < 8; n++) {
            const int jl = tx + 16 * n;
            const bool valid = !(diag && jl <= il);   // strict upper triangle globally
            float s = acc[m][n];
            float posf = fmaf(s, 50.0f, 50.0f);       // (s+1)/step, step = 2/100
            int idx = (int)floorf(posf);
            idx = max(0, min(idx, NBINS - 1));
            float frac = posf - (float)idx;
            frac = fminf(fmaxf(frac, 0.0f), 1.0f);
            int key = idx + ((ci == clsB[jl]) ? 0 : NBINS);
            unsigned q = __float2uint_rn(frac * QSCALE);
            unsigned act = __ballot_sync(0xffffffffu, valid);
            if (valid) {
                unsigned grp = __match_any_sync(act, key);
                unsigned qs  = __reduce_add_sync(grp, q);
                if (lane == __ffs(grp) - 1) {
                    unsigned long long v =
                        ((unsigned long long)__popc(grp) << 40) | (unsigned long long)qs;
                    atomicAdd(&hw[key], v);
                }
            }
        }
    }

    __syncthreads();
    // reduce shared copies -> global accumulators
    for (int i = t; i < NB2; i += THREADS) {
        unsigned long long s = 0ULL;
#pragma unroll
        for (int w = 0; w < NHCOPY; w++) s += whist[w][i];
        if (s != 0ULL) {
            float c = (float)(unsigned)(s >> 40);
            float f = (float)(unsigned long long)(s & QMASK) * (1.0f / QSCALE);
            atomicAdd(&g_cnt[i], c);
            atomicAdd(&g_frc[i], f);
        }
    }
}

__global__ void finalize_kernel(float* out) {
    __shared__ float hp[NBINS], hn[NBINS];
    int t = threadIdx.x;
    if (t < NB2) {
        int b = (t < NBINS) ? t : (t - NBINS);
        float h = g_cnt[t];
        if (b < NBINS - 1) h -= g_frc[t];
        if (b > 0)         h += g_frc[t - 1];
        if (t < NBINS) hp[b] = h; else hn[b] = h;
    }
    __syncthreads();
    if (t == 0) {
        double Sp = 0.0, Sn = 0.0;
#pragma unroll 4
        for (int i = 0; i < NBINS; i++) { Sp += (double)hp[i]; Sn += (double)hn[i]; }
        if (Sp <= 0.0) Sp = 1.0;
        if (Sn <= 0.0) Sn = 1.0;
        double cdf = 0.0, loss = 0.0;
#pragma unroll 4
        for (int j = 0; j < NBINS; j++) {
            cdf  += (double)hp[j];
            loss += (double)hn[j] * cdf;
        }
        out[0] = (float)(loss / (Sp * Sn));
    }
}

extern "C" void kernel_launch(void* const* d_in, const int* in_sizes, int n_in,
                              void* d_out, int out_size) {
    const float* F  = (const float*)d_in[0];
    const void* cls = d_in[1];
    (void)in_sizes; (void)n_in; (void)out_size;

    prep_kernel<<<1, 256>>>((const int*)cls);

    dim3 grid(NF / TILE, NF / TILE);   // 32 x 32, lower-tri blocks early-exit
    pair_hist_kernel<<<grid, THREADS>>>(F, cls);

    finalize_kernel<<<1, 256>>>((float*)d_out);
}